// round 11
// baseline (speedup 1.0000x reference)
#include <cuda_runtime.h>
#include <math.h>

// Problem dims
#define B_   256
#define T_   168
#define LAG_ 168
#define LAT_ 128
#define WS_  64
#define H_   1024

// Step-GEMM tiling
#define BM   32
#define BH   64
#define BKQ  16
#define NTH  128

// Scratch: hidden states hs[0..T], hs[0] = h0 from encoder.
__device__ float g_hs[(T_ + 1) * B_ * H_];
__device__ float g_e1[B_ * 64];
__device__ float g_e2[B_ * LAT_];

typedef unsigned long long ull;

__device__ __forceinline__ ull pk2(float x, float y) {
    ull r; asm("mov.b64 %0, {%1, %2};" : "=l"(r) : "f"(x), "f"(y)); return r;
}
__device__ __forceinline__ void up2(ull v, float& x, float& y) {
    asm("mov.b64 {%0, %1}, %2;" : "=f"(x), "=f"(y) : "l"(v));
}
// packed f32x2 FMA: d = a*b + d (lanewise). Only reachable via PTX fma.rn.f32x2.
__device__ __forceinline__ void fma2(ull& d, ull a, ull b) {
    asm("fma.rn.f32x2 %0, %1, %2, %0;" : "+l"(d) : "l"(a), "l"(b));
}

// ---------------- Encoder MLP (tiny) ----------------

__global__ void enc1_kernel(const float* __restrict__ lag,
                            const float* __restrict__ W1,
                            const float* __restrict__ b1) {
    int idx = blockIdx.x * blockDim.x + threadIdx.x;
    if (idx >= B_ * 64) return;
    int b = idx >> 6, o = idx & 63;
    const float* lr = lag + (size_t)b * LAG_;
    const float* wr = W1 + (size_t)o * LAG_;
    float s = b1[o];
#pragma unroll 4
    for (int k = 0; k < LAG_; k++) s = fmaf(lr[k], wr[k], s);
    g_e1[idx] = (s >= 0.f) ? s : 0.01f * s;
}

__global__ void enc2_kernel(const float* __restrict__ W2,
                            const float* __restrict__ b2) {
    int idx = blockIdx.x * blockDim.x + threadIdx.x;
    if (idx >= B_ * LAT_) return;
    int b = idx / LAT_, o = idx % LAT_;
    const float* er = g_e1 + (size_t)b * 64;
    const float* wr = W2 + (size_t)o * 64;
    float s = b2[o];
#pragma unroll 8
    for (int k = 0; k < 64; k++) s = fmaf(er[k], wr[k], s);
    g_e2[idx] = (s >= 0.f) ? s : 0.01f * s;
}

__global__ void enc3_kernel(const float* __restrict__ W3,
                            const float* __restrict__ b3) {
    int idx = blockIdx.x * blockDim.x + threadIdx.x;
    if (idx >= B_ * H_) return;
    int b = idx >> 10, o = idx & (H_ - 1);
    const float* er = g_e2 + (size_t)b * LAT_;
    const float* wr = W3 + (size_t)o * LAT_;
    float s = b3[o];
#pragma unroll 8
    for (int k = 0; k < LAT_; k++) s = fmaf(er[k], wr[k], s);
    g_hs[idx] = s;   // hs[0] = h0
}

// ---------------- GRU step kernel ----------------
// One launch per timestep. Each CTA computes an h-tile [BM x BH] of h_new.
// It accumulates the three gate pre-activations (r, z combined over both
// phases; hn and inn kept separate as the reference requires) and applies
// the full GRU gate math in the epilogue.

struct Stage {
    float4 a;
    float4 b[6];
};

__device__ __forceinline__ void fetch_stage(Stage& st,
                                            const float* __restrict__ Ap, int lda,
                                            const float* __restrict__ Wp, int ldw,
                                            int k0, int m0, int h0, int tid) {
    int row = tid >> 2;            // 0..31
    int kc  = (tid & 3) << 2;      // 0,4,8,12
    st.a = *(const float4*)(Ap + (size_t)(m0 + row) * lda + k0 + kc);
#pragma unroll
    for (int g = 0; g < 3; g++)
#pragma unroll
        for (int r = 0; r < 2; r++) {
            int hh = row + (r << 5);   // 0..63
            st.b[g * 2 + r] =
                *(const float4*)(Wp + (size_t)(h0 + g * H_ + hh) * ldw + k0 + kc);
        }
}

__device__ __forceinline__ void store_stage(const Stage& st, int tid,
                                            float (&sA)[BKQ][36],
                                            float (&sB)[3][BKQ][68]) {
    int row = tid >> 2;
    int kc  = (tid & 3) << 2;
    sA[kc + 0][row] = st.a.x;
    sA[kc + 1][row] = st.a.y;
    sA[kc + 2][row] = st.a.z;
    sA[kc + 3][row] = st.a.w;
#pragma unroll
    for (int g = 0; g < 3; g++)
#pragma unroll
        for (int r = 0; r < 2; r++) {
            int hh = row + (r << 5);
            float4 v = st.b[g * 2 + r];
            sB[g][kc + 0][hh] = v.x;
            sB[g][kc + 1][hh] = v.y;
            sB[g][kc + 2][hh] = v.z;
            sB[g][kc + 3][hh] = v.w;
        }
}

__device__ __forceinline__ void compute_tile(const float (&sA)[BKQ][36],
                                             const float (&sB)[3][BKQ][68],
                                             int m_off, int h_off,
                                             ull (&aR)[4][2], ull (&aZ)[4][2],
                                             ull (&aN)[4][2]) {
#pragma unroll
    for (int k = 0; k < BKQ; k++) {
        float4 a = *(const float4*)&sA[k][m_off];
        ull pa0 = pk2(a.x, a.x);
        ull pa1 = pk2(a.y, a.y);
        ull pa2 = pk2(a.z, a.z);
        ull pa3 = pk2(a.w, a.w);
        ulonglong2 bR = *(const ulonglong2*)&sB[0][k][h_off];
        ulonglong2 bZ = *(const ulonglong2*)&sB[1][k][h_off];
        ulonglong2 bN = *(const ulonglong2*)&sB[2][k][h_off];

        fma2(aR[0][0], pa0, bR.x); fma2(aR[0][1], pa0, bR.y);
        fma2(aR[1][0], pa1, bR.x); fma2(aR[1][1], pa1, bR.y);
        fma2(aR[2][0], pa2, bR.x); fma2(aR[2][1], pa2, bR.y);
        fma2(aR[3][0], pa3, bR.x); fma2(aR[3][1], pa3, bR.y);

        fma2(aZ[0][0], pa0, bZ.x); fma2(aZ[0][1], pa0, bZ.y);
        fma2(aZ[1][0], pa1, bZ.x); fma2(aZ[1][1], pa1, bZ.y);
        fma2(aZ[2][0], pa2, bZ.x); fma2(aZ[2][1], pa2, bZ.y);
        fma2(aZ[3][0], pa3, bZ.x); fma2(aZ[3][1], pa3, bZ.y);

        fma2(aN[0][0], pa0, bN.x); fma2(aN[0][1], pa0, bN.y);
        fma2(aN[1][0], pa1, bN.x); fma2(aN[1][1], pa1, bN.y);
        fma2(aN[2][0], pa2, bN.x); fma2(aN[2][1], pa2, bN.y);
        fma2(aN[3][0], pa3, bN.x); fma2(aN[3][1], pa3, bN.y);
    }
}

__global__ void __launch_bounds__(NTH, 1)
gru_step_kernel(const float* __restrict__ curr, int t,
                const float* __restrict__ Wih, const float* __restrict__ Whh,
                const float* __restrict__ bih, const float* __restrict__ bhh) {
    __shared__ float sA[2][BKQ][36];
    __shared__ float sB[2][3][BKQ][68];

    const float* x_t    = curr + (size_t)t * B_ * WS_;
    const float* h_prev = g_hs + (size_t)t * B_ * H_;
    float*       h_out  = g_hs + (size_t)(t + 1) * B_ * H_;

    const int tid   = threadIdx.x;
    const int h0    = blockIdx.x * BH;
    const int m0    = blockIdx.y * BM;
    const int m_off = (tid >> 4) << 2;   // 0..28
    const int h_off = (tid & 15) << 2;   // 0..60

    ull aR[4][2], aZ[4][2], aN[4][2], aI[4][2];
#pragma unroll
    for (int i = 0; i < 4; i++) {
        aR[i][0] = aR[i][1] = 0ULL;
        aZ[i][0] = aZ[i][1] = 0ULL;
        aN[i][0] = aN[i][1] = 0ULL;
        aI[i][0] = aI[i][1] = 0ULL;
    }

    Stage st;

    // ---- Phase 0: recurrent GEMM over K = H (Whh) -> aR, aZ, aN ----
    fetch_stage(st, h_prev, H_, Whh, H_, 0, m0, h0, tid);
    store_stage(st, tid, sA[0], sB[0]);
    __syncthreads();
#pragma unroll 1
    for (int k0 = 0; k0 < H_; k0 += BKQ) {
        int buf = (k0 >> 4) & 1;
        bool more = (k0 + BKQ) < H_;
        if (more) fetch_stage(st, h_prev, H_, Whh, H_, k0 + BKQ, m0, h0, tid);
        compute_tile(sA[buf], sB[buf], m_off, h_off, aR, aZ, aN);
        if (more) store_stage(st, tid, sA[buf ^ 1], sB[buf ^ 1]);
        __syncthreads();
    }

    // ---- Phase 1: input GEMM over K = WS (Wih) -> aR, aZ, aI ----
    fetch_stage(st, x_t, WS_, Wih, WS_, 0, m0, h0, tid);
    store_stage(st, tid, sA[0], sB[0]);
    __syncthreads();
#pragma unroll 1
    for (int k0 = 0; k0 < WS_; k0 += BKQ) {
        int buf = (k0 >> 4) & 1;
        bool more = (k0 + BKQ) < WS_;
        if (more) fetch_stage(st, x_t, WS_, Wih, WS_, k0 + BKQ, m0, h0, tid);
        compute_tile(sA[buf], sB[buf], m_off, h_off, aR, aZ, aI);
        if (more) store_stage(st, tid, sA[buf ^ 1], sB[buf ^ 1]);
        __syncthreads();
    }

    // ---- Epilogue: GRU gates + blend ----
#pragma unroll
    for (int i = 0; i < 4; i++) {
        int m = m0 + m_off + i;
#pragma unroll
        for (int p = 0; p < 2; p++) {
            float gr[2], gz[2], gn[2], gi[2];
            up2(aR[i][p], gr[0], gr[1]);
            up2(aZ[i][p], gz[0], gz[1]);
            up2(aN[i][p], gn[0], gn[1]);
            up2(aI[i][p], gi[0], gi[1]);
#pragma unroll
            for (int q = 0; q < 2; q++) {
                int j = h0 + h_off + 2 * p + q;
                float pre_r = gr[q] + bih[j] + bhh[j];
                float pre_z = gz[q] + bih[H_ + j] + bhh[H_ + j];
                float hn    = gn[q] + bhh[2 * H_ + j];
                float inn   = gi[q] + bih[2 * H_ + j];
                float r = 1.f / (1.f + expf(-pre_r));
                float z = 1.f / (1.f + expf(-pre_z));
                float n = tanhf(inn + r * hn);
                float hp = h_prev[(size_t)m * H_ + j];
                h_out[(size_t)m * H_ + j] = (1.f - z) * n + z * hp;
            }
        }
    }
}

// ---------------- Output projection: preds[b][t] = hs[t+1][b] . Wo + bo ----------------

__global__ void pred_kernel(const float* __restrict__ Wo,
                            const float* __restrict__ bo,
                            float* __restrict__ out) {
    int gw = (blockIdx.x * blockDim.x + threadIdx.x) >> 5;
    int lane = threadIdx.x & 31;
    if (gw >= T_ * B_) return;
    int t = gw / B_, b = gw % B_;
    const float* h = g_hs + ((size_t)(t + 1) * B_ + b) * H_;
    float s = 0.f;
#pragma unroll 8
    for (int k = lane; k < H_; k += 32) s = fmaf(h[k], Wo[k], s);
#pragma unroll
    for (int o = 16; o; o >>= 1) s += __shfl_xor_sync(0xffffffffu, s, o);
    if (lane == 0) out[(size_t)b * T_ + t] = s + bo[0];
}

// ---------------- Launch ----------------

extern "C" void kernel_launch(void* const* d_in, const int* in_sizes, int n_in,
                              void* d_out, int out_size) {
    const float* lag  = (const float*)d_in[0];
    const float* curr = (const float*)d_in[1];
    const float* W1   = (const float*)d_in[2];
    const float* b1   = (const float*)d_in[3];
    const float* W2   = (const float*)d_in[4];
    const float* b2   = (const float*)d_in[5];
    const float* W3   = (const float*)d_in[6];
    const float* b3   = (const float*)d_in[7];
    const float* Wih  = (const float*)d_in[8];
    const float* Whh  = (const float*)d_in[9];
    const float* bih  = (const float*)d_in[10];
    const float* bhh  = (const float*)d_in[11];
    const float* Wo   = (const float*)d_in[12];
    const float* bo   = (const float*)d_in[13];
    float* out = (float*)d_out;

    enc1_kernel<<<(B_ * 64 + 255) / 256, 256>>>(lag, W1, b1);
    enc2_kernel<<<(B_ * LAT_ + 255) / 256, 256>>>(W2, b2);
    enc3_kernel<<<(B_ * H_ + 255) / 256, 256>>>(W3, b3);

    dim3 grid(H_ / BH, B_ / BM);   // (16, 8) = 128 CTAs
    for (int t = 0; t < T_; t++) {
        gru_step_kernel<<<grid, NTH>>>(curr, t, Wih, Whh, bih, bhh);
    }

    int warps = T_ * B_;
    pred_kernel<<<(warps * 32 + 255) / 256, 256>>>(Wo, bo, out);
}